// round 1
// baseline (speedup 1.0000x reference)
#include <cuda_runtime.h>
#include <math.h>

#define S3 262144        // 64^3
#define CH 64
#define NMODE 6912       // 24*24*12

// ---------------- scratch (static device globals; no allocation) ----------------
__device__ float  g_v[CH*S3];              // current activation (C,D,H,W)
__device__ float  g_s[CH*S3];              // x1 then x1+x2
__device__ float2 g_A[CH*64*12*64];        // (c,d,kw,h)
__device__ float2 g_B[CH*24*12*64];        // (c,jh,kw,d)
__device__ float2 g_X[CH*NMODE];           // (c, jd*288+jh*12+kw)
__device__ float2 g_Y[CH*NMODE];
__device__ float  g_h1[1024];
__device__ float  g_film[384];             // (l,c,2)
__device__ double g_gn[16];                // 8 groups x (sum, sumsq)
__device__ float  g_gnf[16];               // 8 groups x (mu, rsig)
__device__ float2 tw_fW[12*64];            // [kw][w] e^{-i 2pi kw w/64}
__device__ float2 tw_iW[12*64];            // [kw][w] alpha*(cos,sin)/64^3
__device__ float2 tw_fDH[24*64];           // [j][x]  e^{-i 2pi bin(j) x/64}
__device__ float2 tw_iDH[24*64];           // [j][x]  e^{+i ...}

__device__ __forceinline__ float gelu_f(float x){
    return 0.5f*x*(1.0f + erff(x*0.7071067811865476f));
}

// ---------------- tables ----------------
__global__ void init_tables_k(){
    int t = blockIdx.x*blockDim.x + threadIdx.x;
    const double w0 = 6.283185307179586476925286766559/64.0;
    if(t < 768){
        int kw = t>>6, w = t&63;
        double s,c; sincos(w0*(double)(kw*w), &s, &c);
        tw_fW[t] = make_float2((float)c, (float)(-s));
        double al = (kw==0 ? 1.0 : 2.0) / 262144.0;
        tw_iW[t] = make_float2((float)(al*c), (float)(al*s));
    }
    if(t < 1536){
        int j = t>>6, x = t&63;
        int bin = (j<12) ? j : (j+40);           // 0..11, 52..63
        double s,c; sincos(w0*(double)(bin*x), &s, &c);
        tw_fDH[t] = make_float2((float)c, (float)(-s));
        tw_iDH[t] = make_float2((float)c, (float)( s));
    }
}

// ---------------- FiLM conditioner ----------------
__global__ void film1_k(const float* __restrict__ latent, const float* __restrict__ w,
                        const float* __restrict__ b){
    int wid  = (blockIdx.x*blockDim.x + threadIdx.x) >> 5;
    int lane = threadIdx.x & 31;
    if(wid >= 1024) return;
    const float* wr = w + wid*512;
    float acc = 0.f;
    for(int k=lane;k<512;k+=32) acc += latent[k]*wr[k];
    #pragma unroll
    for(int o=16;o;o>>=1) acc += __shfl_xor_sync(0xffffffffu, acc, o);
    if(lane==0) g_h1[wid] = gelu_f(acc + b[wid]);
}
__global__ void film2_k(const float* __restrict__ w, const float* __restrict__ b){
    int wid  = (blockIdx.x*blockDim.x + threadIdx.x) >> 5;
    int lane = threadIdx.x & 31;
    if(wid >= 384) return;
    const float* wr = w + wid*1024;
    float acc = 0.f;
    for(int k=lane;k<1024;k+=32) acc += g_h1[k]*wr[k];
    #pragma unroll
    for(int o=16;o;o>>=1) acc += __shfl_xor_sync(0xffffffffu, acc, o);
    if(lane==0) g_film[wid] = acc + b[wid];
}

// ---------------- lift ----------------
__global__ void lift_k(const float* __restrict__ x, const float* __restrict__ w,
                       const float* __restrict__ b){
    int s = blockIdx.x*256 + threadIdx.x;
    int c = blockIdx.y;
    float r = b[c] + w[c*4+0]*x[s] + w[c*4+1]*x[S3+s]
                   + w[c*4+2]*x[2*S3+s] + w[c*4+3]*x[3*S3+s];
    g_v[c*S3+s] = r;
}

// ---------------- forward truncated DFTs ----------------
__global__ void __launch_bounds__(256) fwdW_k(){
    int c = blockIdx.y, d = blockIdx.x;
    __shared__ float  vsh[64][65];
    __shared__ float2 tws[12][64];
    const float* src = g_v + (c*64+d)*4096;
    for(int i=threadIdx.x;i<4096;i+=256) vsh[i>>6][i&63] = src[i];
    for(int i=threadIdx.x;i<768;i+=256)  ((float2*)tws)[i] = tw_fW[i];
    __syncthreads();
    int h = threadIdx.x & 63, k0 = threadIdx.x >> 6;
    for(int kw=k0; kw<12; kw+=4){
        float re=0.f, im=0.f;
        #pragma unroll 8
        for(int w=0;w<64;w++){
            float v = vsh[h][w]; float2 t = tws[kw][w];
            re += v*t.x; im += v*t.y;
        }
        g_A[((c*64+d)*12+kw)*64 + h] = make_float2(re, im);
    }
}

__global__ void __launch_bounds__(256) fwdH_k(){
    int c = blockIdx.y, d = blockIdx.x;
    __shared__ float2 ash[12][64];   // [kw][h]
    __shared__ float2 tws[24][64];
    const float2* src = g_A + (c*64+d)*768;
    for(int i=threadIdx.x;i<768;i+=256)  ((float2*)ash)[i] = src[i];
    for(int i=threadIdx.x;i<1536;i+=256) ((float2*)tws)[i] = tw_fDH[i];
    __syncthreads();
    for(int idx=threadIdx.x; idx<288; idx+=256){
        int jh = idx/12, kw = idx-jh*12;
        float re=0.f, im=0.f;
        #pragma unroll 8
        for(int h=0;h<64;h++){
            float2 a = ash[kw][h]; float2 t = tws[jh][h];
            re += a.x*t.x - a.y*t.y;
            im += a.x*t.y + a.y*t.x;
        }
        g_B[((c*24+jh)*12+kw)*64 + d] = make_float2(re, im);
    }
}

__global__ void __launch_bounds__(256) fwdD_k(){
    int c = blockIdx.y, jh = blockIdx.x;  // jh 0..23
    __shared__ float2 bsh[12][64];   // [kw][d]
    __shared__ float2 tws[24][64];
    const float2* src = g_B + (c*24+jh)*768;
    for(int i=threadIdx.x;i<768;i+=256)  ((float2*)bsh)[i] = src[i];
    for(int i=threadIdx.x;i<1536;i+=256) ((float2*)tws)[i] = tw_fDH[i];
    __syncthreads();
    for(int idx=threadIdx.x; idx<288; idx+=256){
        int jd = idx/12, kw = idx-jd*12;
        float re=0.f, im=0.f;
        #pragma unroll 8
        for(int d=0;d<64;d++){
            float2 bv = bsh[kw][d]; float2 t = tws[jd][d];
            re += bv.x*t.x - bv.y*t.y;
            im += bv.x*t.y + bv.y*t.x;
        }
        g_X[c*NMODE + (jd*24+jh)*12 + kw] = make_float2(re, im);
    }
}

// ---------------- per-mode channel mix (HBM streaming bottleneck) ----------------
__global__ void __launch_bounds__(256) mix_k(const float* __restrict__ w1, const float* __restrict__ w2,
                                             const float* __restrict__ w3, const float* __restrict__ w4){
    int m0 = blockIdx.x*64;
    __shared__ float2 xs[64][64];    // [i][local mode]
    int tx = threadIdx.x & 63, ty = threadIdx.x >> 6;
    for(int i=ty;i<64;i+=4) xs[i][tx] = g_X[i*NMODE + m0 + tx];
    __syncthreads();
    int mode = m0 + tx;
    int jd = mode/288; int r = mode - jd*288; int jh = r/12; int kw = r - jh*12;
    const float* wbase = (jd<12) ? (jh<12 ? w1 : w3) : (jh<12 ? w2 : w4);
    int cmode = ((jd%12)*12 + (jh%12))*12 + kw;
    const float2* W = (const float2*)wbase + cmode;   // element (i,o) at +(i*64+o)*1728
    #pragma unroll
    for(int oi=0; oi<4; oi++){
        int o = blockIdx.y*16 + ty*4 + oi;
        const float2* Wo = W + o*1728;
        float re=0.f, im=0.f;
        #pragma unroll 4
        for(int i=0;i<64;i++){
            float2 w = __ldg(&Wo[i*110592]);
            float2 x = xs[i][tx];
            re += x.x*w.x - x.y*w.y;
            im += x.x*w.y + x.y*w.x;
        }
        g_Y[o*NMODE + mode] = make_float2(re, im);
    }
}

// ---------------- inverse DFTs ----------------
__global__ void __launch_bounds__(256) invD_k(){
    int c = blockIdx.y, jh = blockIdx.x;   // jh 0..23
    __shared__ float2 ysh[24][12];
    __shared__ float2 tws[24][64];
    for(int i=threadIdx.x;i<288;i+=256){
        int jd = i/12, kw = i-jd*12;
        ysh[jd][kw] = g_Y[c*NMODE + (jd*24+jh)*12 + kw];
    }
    for(int i=threadIdx.x;i<1536;i+=256) ((float2*)tws)[i] = tw_iDH[i];
    __syncthreads();
    int d = threadIdx.x & 63, k0 = threadIdx.x >> 6;
    for(int kw=k0; kw<12; kw+=4){
        float re=0.f, im=0.f;
        #pragma unroll
        for(int jd=0;jd<24;jd++){
            float2 y = ysh[jd][kw]; float2 t = tws[jd][d];
            re += y.x*t.x - y.y*t.y;
            im += y.x*t.y + y.y*t.x;
        }
        g_B[((c*24+jh)*12+kw)*64 + d] = make_float2(re, im);
    }
}

__global__ void __launch_bounds__(256) invH_k(){
    int c = blockIdx.y, d = blockIdx.x;
    __shared__ float2 bsh[24][12];
    __shared__ float2 tws[24][64];
    for(int i=threadIdx.x;i<288;i+=256){
        int jh = i/12, kw = i-jh*12;
        bsh[jh][kw] = g_B[((c*24+jh)*12+kw)*64 + d];
    }
    for(int i=threadIdx.x;i<1536;i+=256) ((float2*)tws)[i] = tw_iDH[i];
    __syncthreads();
    int h = threadIdx.x & 63, k0 = threadIdx.x >> 6;
    for(int kw=k0; kw<12; kw+=4){
        float re=0.f, im=0.f;
        #pragma unroll
        for(int jh=0;jh<24;jh++){
            float2 bv = bsh[jh][kw]; float2 t = tws[jh][h];
            re += bv.x*t.x - bv.y*t.y;
            im += bv.x*t.y + bv.y*t.x;
        }
        g_A[((c*64+d)*12+kw)*64 + h] = make_float2(re, im);
    }
}

__global__ void __launch_bounds__(256) invW_k(){
    int c = blockIdx.y, d = blockIdx.x;
    __shared__ float2 ash[12][64];   // [kw][h]
    __shared__ float2 tws[12][64];   // [kw][w] (alpha*cos, alpha*sin)/64^3
    const float2* src = g_A + (c*64+d)*768;
    for(int i=threadIdx.x;i<768;i+=256){ ((float2*)ash)[i] = src[i]; ((float2*)tws)[i] = tw_iW[i]; }
    __syncthreads();
    int w = threadIdx.x & 63, h0 = threadIdx.x >> 6;
    for(int h=h0; h<64; h+=4){
        float acc = 0.f;
        #pragma unroll
        for(int kw=0;kw<12;kw++){
            float2 a = ash[kw][h]; float2 t = tws[kw][w];
            acc += a.x*t.x - a.y*t.y;       // Re*c - Im*s
        }
        g_s[(c*64+d)*4096 + h*64 + w] = acc;
    }
}

// ---------------- conv1x1 + add + GN stats ----------------
__global__ void zero_gn_k(){ if(threadIdx.x<16) g_gn[threadIdx.x]=0.0; }

__global__ void __launch_bounds__(256) conv_gn_k(const float* __restrict__ cw, const float* __restrict__ cb){
    int s0 = blockIdx.x*64;
    __shared__ float vsh[64][65];
    __shared__ float wsh[64][64];
    __shared__ float gpart[16];
    int t = threadIdx.x & 63, og = threadIdx.x >> 6;
    for(int i=og;i<64;i+=4) vsh[i][t] = g_v[i*S3 + s0 + t];
    for(int i=threadIdx.x;i<4096;i+=256) wsh[i>>6][i&63] = cw[i];
    if(threadIdx.x<16) gpart[threadIdx.x]=0.f;
    __syncthreads();
    float s0a=0.f,q0a=0.f,s1a=0.f,q1a=0.f;
    for(int k=0;k<16;k++){
        int o = og*16 + k;
        float acc = cb[o];
        #pragma unroll
        for(int i=0;i<64;i++) acc += vsh[i][t]*wsh[o][i];
        int idx = o*S3 + s0 + t;
        float sv = g_s[idx] + acc;
        g_s[idx] = sv;
        if(k<8){ s0a+=sv; q0a+=sv*sv; } else { s1a+=sv; q1a+=sv*sv; }
    }
    atomicAdd(&gpart[og*4+0], s0a);
    atomicAdd(&gpart[og*4+1], q0a);
    atomicAdd(&gpart[og*4+2], s1a);
    atomicAdd(&gpart[og*4+3], q1a);
    __syncthreads();
    if(threadIdx.x<16) atomicAdd(&g_gn[threadIdx.x], (double)gpart[threadIdx.x]);
}

__global__ void gn_final_k(){
    int g = threadIdx.x;
    if(g<8){
        double n = 8.0*(double)S3;
        double mu = g_gn[g*2]/n;
        double var = g_gn[g*2+1]/n - mu*mu;
        g_gnf[g*2]   = (float)mu;
        g_gnf[g*2+1] = (float)(1.0/sqrt(var + 1e-5));
    }
}

__global__ void gn_apply_k(const float* __restrict__ gg, const float* __restrict__ gb, int l){
    int s = blockIdx.x*256 + threadIdx.x;
    int c = blockIdx.y;
    int g = c >> 3;
    float mu = g_gnf[g*2], rs = g_gnf[g*2+1];
    float x = (g_s[c*S3+s]-mu)*rs*gg[c] + gb[c];
    float y = gelu_f(x);
    float sc = g_film[(l*64+c)*2], sh = g_film[(l*64+c)*2+1];
    g_v[c*S3+s] = y*(1.0f+sc) + sh;
}

// ---------------- fused head: p1 (gelu) + p2 ----------------
__global__ void __launch_bounds__(256) head_k(const float* __restrict__ w1, const float* __restrict__ b1,
                                              const float* __restrict__ w2, const float* __restrict__ b2,
                                              float* __restrict__ out){
    int s0 = blockIdx.x*64;
    __shared__ float vsh[64][65];
    __shared__ float red[3][4][64];
    int t = threadIdx.x & 63, q = threadIdx.x >> 6;
    for(int i=q;i<64;i+=4) vsh[i][t] = g_v[i*S3 + s0 + t];
    __syncthreads();
    float a0=0.f,a1=0.f,a2=0.f;
    for(int o2=q*32; o2<q*32+32; o2++){
        float acc = __ldg(&b1[o2]);
        const float* wr = w1 + o2*64;
        #pragma unroll
        for(int i=0;i<64;i++) acc += vsh[i][t]*__ldg(&wr[i]);
        float u = gelu_f(acc);
        a0 += u*__ldg(&w2[o2]);
        a1 += u*__ldg(&w2[128+o2]);
        a2 += u*__ldg(&w2[256+o2]);
    }
    red[0][q][t]=a0; red[1][q][t]=a1; red[2][q][t]=a2;
    __syncthreads();
    if(q==0){
        #pragma unroll
        for(int j=0;j<3;j++){
            float r = red[j][0][t]+red[j][1][t]+red[j][2][t]+red[j][3][t] + b2[j];
            out[j*S3 + s0 + t] = r;
        }
    }
}

// ---------------- launch ----------------
extern "C" void kernel_launch(void* const* d_in, const int* in_sizes, int n_in,
                              void* d_out, int out_size){
    const float* x      = (const float*)d_in[0];
    const float* latent = (const float*)d_in[1];
    const float* lift_w = (const float*)d_in[2];
    const float* lift_b = (const float*)d_in[3];
    const float* sc_w1  = (const float*)d_in[4];
    const float* sc_w2  = (const float*)d_in[5];
    const float* sc_w3  = (const float*)d_in[6];
    const float* sc_w4  = (const float*)d_in[7];
    const float* conv_w = (const float*)d_in[8];
    const float* conv_b = (const float*)d_in[9];
    const float* gn_g   = (const float*)d_in[10];
    const float* gn_b   = (const float*)d_in[11];
    const float* p1_w   = (const float*)d_in[12];
    const float* p1_b   = (const float*)d_in[13];
    const float* p2_w   = (const float*)d_in[14];
    const float* p2_b   = (const float*)d_in[15];
    const float* c1_w   = (const float*)d_in[16];
    const float* c1_b   = (const float*)d_in[17];
    const float* c2_w   = (const float*)d_in[18];
    const float* c2_b   = (const float*)d_in[19];
    float* out = (float*)d_out;

    init_tables_k<<<6,256>>>();
    film1_k<<<128,256>>>(latent, c1_w, c1_b);
    film2_k<<<48,256>>>(c2_w, c2_b);
    lift_k<<<dim3(1024,64),256>>>(x, lift_w, lift_b);

    const size_t WOFF = (size_t)64*64*12*12*12*2;  // per-layer spectral weight floats
    for(int l=0;l<3;l++){
        fwdW_k<<<dim3(64,64),256>>>();
        fwdH_k<<<dim3(64,64),256>>>();
        fwdD_k<<<dim3(24,64),256>>>();
        mix_k<<<dim3(108,4),256>>>(sc_w1 + l*WOFF, sc_w2 + l*WOFF,
                                   sc_w3 + l*WOFF, sc_w4 + l*WOFF);
        invD_k<<<dim3(24,64),256>>>();
        invH_k<<<dim3(64,64),256>>>();
        invW_k<<<dim3(64,64),256>>>();
        zero_gn_k<<<1,16>>>();
        conv_gn_k<<<4096,256>>>(conv_w + l*4096, conv_b + l*64);
        gn_final_k<<<1,8>>>();
        gn_apply_k<<<dim3(1024,64),256>>>(gn_g + l*64, gn_b + l*64, l);
    }
    head_k<<<4096,256>>>(p1_w, p1_b, p2_w, p2_b, out);
}

// round 2
// speedup vs baseline: 1.5976x; 1.5976x over previous
#include <cuda_runtime.h>
#include <math.h>

#define S3 262144        // 64^3
#define CH 64
#define NMODE 6912       // 24*24*12

// ---------------- scratch ----------------
__device__ float  g_v[CH*S3];              // activation (c, d,h,w)
__device__ float  g_s[CH*S3];              // x2 then x1+x2
__device__ float2 g_B[CH*64*288];          // fwd: (c,d, jh*12+kw) ; inv: same layout
__device__ float2 g_X[CH*NMODE];           // (c, (jd*24+jh)*12+kw)
__device__ float2 g_Y[CH*NMODE];
__device__ float  g_h1[1024];
__device__ float  g_film[384];
__device__ double g_gn[16];                // 8 groups x (sum, sumsq)
__device__ float  g_gnf[16];               // 8 groups x (mu, rsig)
__device__ float2 tw_fW[12*64];
__device__ float2 tw_iW[12*64];            // includes alpha/64^3
__device__ float2 tw_fDH[24*64];
__device__ float2 tw_iDH[24*64];

__device__ __forceinline__ float gelu_f(float x){
    return 0.5f*x*(1.0f + erff(x*0.7071067811865476f));
}

// ---------------- tables (+ zero GN accumulators) ----------------
__global__ void init_tables_k(){
    int t = blockIdx.x*blockDim.x + threadIdx.x;
    const double w0 = 6.283185307179586476925286766559/64.0;
    if(t < 768){
        int kw = t>>6, w = t&63;
        double s,c; sincos(w0*(double)(kw*w), &s, &c);
        tw_fW[t] = make_float2((float)c, (float)(-s));
        double al = (kw==0 ? 1.0 : 2.0) / 262144.0;
        tw_iW[t] = make_float2((float)(al*c), (float)(al*s));
    }
    if(t < 1536){
        int j = t>>6, x = t&63;
        int bin = (j<12) ? j : (j+40);
        double s,c; sincos(w0*(double)(bin*x), &s, &c);
        tw_fDH[t] = make_float2((float)c, (float)(-s));
        tw_iDH[t] = make_float2((float)c, (float)( s));
    }
    if(t < 16) g_gn[t] = 0.0;
}

// ---------------- FiLM ----------------
__global__ void film1_k(const float* __restrict__ latent, const float* __restrict__ w,
                        const float* __restrict__ b){
    int wid  = (blockIdx.x*blockDim.x + threadIdx.x) >> 5;
    int lane = threadIdx.x & 31;
    if(wid >= 1024) return;
    const float* wr = w + wid*512;
    float acc = 0.f;
    for(int k=lane;k<512;k+=32) acc += latent[k]*wr[k];
    #pragma unroll
    for(int o=16;o;o>>=1) acc += __shfl_xor_sync(0xffffffffu, acc, o);
    if(lane==0) g_h1[wid] = gelu_f(acc + b[wid]);
}
__global__ void film2_k(const float* __restrict__ w, const float* __restrict__ b){
    int wid  = (blockIdx.x*blockDim.x + threadIdx.x) >> 5;
    int lane = threadIdx.x & 31;
    if(wid >= 384) return;
    const float* wr = w + wid*1024;
    float acc = 0.f;
    for(int k=lane;k<1024;k+=32) acc += g_h1[k]*wr[k];
    #pragma unroll
    for(int o=16;o;o>>=1) acc += __shfl_xor_sync(0xffffffffu, acc, o);
    if(lane==0) g_film[wid] = acc + b[wid];
}

// ---------------- lift + conv(layer0) fused ----------------
__global__ void __launch_bounds__(256) lift_conv_k(const float* __restrict__ x,
        const float* __restrict__ lw, const float* __restrict__ lb,
        const float* __restrict__ cw, const float* __restrict__ cb){
    int s0 = blockIdx.x*64;
    __shared__ float xsh[4][64];
    __shared__ float vsh[64][65];
    __shared__ float wsh[64][64];
    int t = threadIdx.x & 63, og = threadIdx.x >> 6;
    if(threadIdx.x < 256){
        int r = threadIdx.x >> 6, c0 = threadIdx.x & 63;
        xsh[r][c0] = x[(size_t)r*S3 + s0 + c0];
    }
    for(int i=threadIdx.x;i<4096;i+=256) wsh[i>>6][i&63] = cw[i];
    __syncthreads();
    #pragma unroll
    for(int k=0;k<16;k++){
        int c = og*16+k;
        float r = __ldg(&lb[c]) + __ldg(&lw[c*4+0])*xsh[0][t] + __ldg(&lw[c*4+1])*xsh[1][t]
                                + __ldg(&lw[c*4+2])*xsh[2][t] + __ldg(&lw[c*4+3])*xsh[3][t];
        vsh[c][t] = r;
        g_v[(size_t)c*S3 + s0 + t] = r;
    }
    __syncthreads();
    for(int k=0;k<16;k++){
        int o = og*16+k;
        float acc = __ldg(&cb[o]);
        #pragma unroll
        for(int i=0;i<64;i++) acc += vsh[i][t]*wsh[o][i];
        g_s[(size_t)o*S3 + s0 + t] = acc;
    }
}

// ---------------- fused forward DFT: W then H ----------------
__global__ void __launch_bounds__(256) fwdWH_k(){
    int d = blockIdx.x, c = blockIdx.y;
    __shared__ float  vsh[64][65];    // [h][w]
    __shared__ float2 Ash[12][65];    // [kw][h]
    __shared__ float2 twW[12*64];
    __shared__ float2 twH[24*64];
    const float4* src = (const float4*)(g_v + (size_t)(c*64+d)*4096);
    for(int i=threadIdx.x;i<1024;i+=256){
        float4 v4 = src[i];
        int h = i>>4, w4 = (i&15)*4;
        vsh[h][w4]=v4.x; vsh[h][w4+1]=v4.y; vsh[h][w4+2]=v4.z; vsh[h][w4+3]=v4.w;
    }
    for(int i=threadIdx.x;i<768;i+=256)  twW[i]=tw_fW[i];
    for(int i=threadIdx.x;i<1536;i+=256) twH[i]=tw_fDH[i];
    __syncthreads();
    int h = threadIdx.x & 63, q = threadIdx.x >> 6;
    #pragma unroll
    for(int kw=q; kw<12; kw+=4){
        float re=0.f, im=0.f;
        #pragma unroll 8
        for(int w=0;w<64;w++){
            float v = vsh[h][w]; float2 tt = twW[kw*64+w];
            re += v*tt.x; im += v*tt.y;
        }
        Ash[kw][h] = make_float2(re,im);
    }
    __syncthreads();
    float2* dst = g_B + (size_t)(c*64+d)*288;
    for(int idx=threadIdx.x; idx<288; idx+=256){
        int jh = idx/12, kw = idx-jh*12;
        float re=0.f, im=0.f;
        #pragma unroll 8
        for(int hh=0;hh<64;hh++){
            float2 a = Ash[kw][hh]; float2 tt = twH[jh*64+hh];
            re += a.x*tt.x - a.y*tt.y;
            im += a.x*tt.y + a.y*tt.x;
        }
        dst[idx] = make_float2(re,im);
    }
}

// ---------------- forward DFT over D ----------------
__global__ void __launch_bounds__(256) fwdD_k(){
    int jh = blockIdx.x, c = blockIdx.y;
    __shared__ float2 Bsh[64][12];
    __shared__ float2 twD[24*64];
    for(int idx=threadIdx.x; idx<768; idx+=256){
        int d = idx/12, kw = idx-d*12;
        Bsh[d][kw] = g_B[(size_t)(c*64+d)*288 + jh*12 + kw];
    }
    for(int i=threadIdx.x;i<1536;i+=256) twD[i]=tw_fDH[i];
    __syncthreads();
    for(int idx=threadIdx.x; idx<288; idx+=256){
        int jd = idx/12, kw = idx-jd*12;
        float re=0.f, im=0.f;
        #pragma unroll 8
        for(int d=0;d<64;d++){
            float2 b = Bsh[d][kw]; float2 tt = twD[jd*64+d];
            re += b.x*tt.x - b.y*tt.y;
            im += b.x*tt.y + b.y*tt.x;
        }
        g_X[c*NMODE + (jd*24+jh)*12 + kw] = make_float2(re,im);
    }
}

// ---------------- per-mode channel mix ----------------
__global__ void __launch_bounds__(256) mix_k(const float* __restrict__ w1, const float* __restrict__ w2,
                                             const float* __restrict__ w3, const float* __restrict__ w4){
    int m0 = blockIdx.x*64;
    __shared__ float2 xs[64][64];
    int tx = threadIdx.x & 63, ty = threadIdx.x >> 6;
    for(int i=ty;i<64;i+=4) xs[i][tx] = g_X[i*NMODE + m0 + tx];
    __syncthreads();
    int mode = m0 + tx;
    int jd = mode/288; int r = mode - jd*288; int jh = r/12; int kw = r - jh*12;
    const float* wbase = (jd<12) ? (jh<12 ? w1 : w3) : (jh<12 ? w2 : w4);
    int cmode = ((jd%12)*12 + (jh%12))*12 + kw;
    const float2* W = (const float2*)wbase + cmode;
    int o0 = blockIdx.y*8 + ty*2;
    const float2* W0 = W + (size_t)o0*1728;
    const float2* W1 = W0 + 1728;
    float re0=0.f,im0=0.f,re1=0.f,im1=0.f;
    #pragma unroll 4
    for(int i=0;i<64;i++){
        float2 xv = xs[i][tx];
        float2 wa = __ldg(W0 + (size_t)i*110592);
        float2 wb = __ldg(W1 + (size_t)i*110592);
        re0 += xv.x*wa.x - xv.y*wa.y; im0 += xv.x*wa.y + xv.y*wa.x;
        re1 += xv.x*wb.x - xv.y*wb.y; im1 += xv.x*wb.y + xv.y*wb.x;
    }
    g_Y[(size_t)o0*NMODE + mode]     = make_float2(re0,im0);
    g_Y[(size_t)(o0+1)*NMODE + mode] = make_float2(re1,im1);
}

// ---------------- inverse DFT over D ----------------
__global__ void __launch_bounds__(256) invD_k(){
    int jh = blockIdx.x, c = blockIdx.y;
    __shared__ float2 Ysh[24][12];
    __shared__ float2 twD[24*64];
    for(int idx=threadIdx.x; idx<288; idx+=256){
        int jd = idx/12, kw = idx-jd*12;
        Ysh[jd][kw] = g_Y[(size_t)c*NMODE + (jd*24+jh)*12 + kw];
    }
    for(int i=threadIdx.x;i<1536;i+=256) twD[i]=tw_iDH[i];
    __syncthreads();
    for(int idx=threadIdx.x; idx<768; idx+=256){
        int d = idx/12, kw = idx-d*12;
        float re=0.f, im=0.f;
        #pragma unroll
        for(int jd=0;jd<24;jd++){
            float2 y = Ysh[jd][kw]; float2 tt = twD[jd*64+d];
            re += y.x*tt.x - y.y*tt.y;
            im += y.x*tt.y + y.y*tt.x;
        }
        g_B[(size_t)(c*64+d)*288 + jh*12 + kw] = make_float2(re,im);
    }
}

// ---------------- fused inverse H + W + residual add + GN stats ----------------
__global__ void __launch_bounds__(256) invHW_gn_k(){
    int d = blockIdx.x, c = blockIdx.y;
    __shared__ float2 Bsh[288];
    __shared__ float2 Ash[12][65];
    __shared__ float2 twH[24*64];
    __shared__ float2 twW[12*64];
    __shared__ float redS[8], redQ[8];
    const float2* src = g_B + (size_t)(c*64+d)*288;
    for(int i=threadIdx.x;i<288;i+=256) Bsh[i]=src[i];
    for(int i=threadIdx.x;i<1536;i+=256) twH[i]=tw_iDH[i];
    for(int i=threadIdx.x;i<768;i+=256)  twW[i]=tw_iW[i];
    __syncthreads();
    int h = threadIdx.x & 63, q = threadIdx.x >> 6;
    #pragma unroll
    for(int kw=q; kw<12; kw+=4){
        float re=0.f, im=0.f;
        #pragma unroll
        for(int jh=0;jh<24;jh++){
            float2 b = Bsh[jh*12+kw]; float2 tt = twH[jh*64+h];
            re += b.x*tt.x - b.y*tt.y;
            im += b.x*tt.y + b.y*tt.x;
        }
        Ash[kw][h] = make_float2(re,im);
    }
    __syncthreads();
    int w = threadIdx.x & 63;
    float ssum=0.f, sq=0.f;
    float* dst = g_s + (size_t)c*S3 + d*4096;
    for(int hh=q; hh<64; hh+=4){
        float acc = 0.f;
        #pragma unroll
        for(int kw=0;kw<12;kw++){
            float2 a = Ash[kw][hh]; float2 tt = twW[kw*64+w];
            acc += a.x*tt.x - a.y*tt.y;
        }
        float sv = dst[hh*64+w] + acc;
        dst[hh*64+w] = sv;
        ssum += sv; sq += sv*sv;
    }
    #pragma unroll
    for(int o=16;o;o>>=1){ ssum += __shfl_xor_sync(0xffffffffu,ssum,o);
                           sq   += __shfl_xor_sync(0xffffffffu,sq,o); }
    int warp = threadIdx.x>>5, lane = threadIdx.x&31;
    if(lane==0){ redS[warp]=ssum; redQ[warp]=sq; }
    __syncthreads();
    if(threadIdx.x==0){
        float S=0.f,Q=0.f;
        #pragma unroll
        for(int i=0;i<8;i++){S+=redS[i];Q+=redQ[i];}
        int g = c>>3;
        atomicAdd(&g_gn[g*2],   (double)S);
        atomicAdd(&g_gn[g*2+1], (double)Q);
    }
}

__global__ void gn_final_k(){
    int g = threadIdx.x;
    float mu_f=0.f, rs_f=0.f;
    if(g<8){
        double n = 8.0*(double)S3;
        double mu = g_gn[g*2]/n;
        double var = g_gn[g*2+1]/n - mu*mu;
        mu_f = (float)mu; rs_f = (float)(1.0/sqrt(var + 1e-5));
    }
    __syncthreads();
    if(g<8){ g_gnf[g*2]=mu_f; g_gnf[g*2+1]=rs_f; }
    if(g<16) g_gn[g]=0.0;
}

// ---------------- GN-apply + GELU + FiLM + conv(next layer) ----------------
__global__ void __launch_bounds__(256) gn_apply_conv_k(const float* __restrict__ gg, const float* __restrict__ gb,
        int l, const float* __restrict__ cw, const float* __restrict__ cb){
    int s0 = blockIdx.x*64;
    __shared__ float vsh[64][65];
    __shared__ float wsh[64][64];
    int t = threadIdx.x & 63, og = threadIdx.x >> 6;
    for(int i=threadIdx.x;i<4096;i+=256) wsh[i>>6][i&63]=cw[i];
    #pragma unroll
    for(int k=0;k<16;k++){
        int c = og*16+k;
        int g = c>>3;
        float mu = g_gnf[g*2], rs = g_gnf[g*2+1];
        float xv = (g_s[(size_t)c*S3+s0+t]-mu)*rs*__ldg(&gg[c]) + __ldg(&gb[c]);
        float y = gelu_f(xv);
        float sc = g_film[(l*64+c)*2], sh = g_film[(l*64+c)*2+1];
        float v = y*(1.f+sc)+sh;
        vsh[c][t]=v;
        g_v[(size_t)c*S3+s0+t]=v;
    }
    __syncthreads();
    for(int k=0;k<16;k++){
        int o = og*16+k;
        float acc = __ldg(&cb[o]);
        #pragma unroll
        for(int i=0;i<64;i++) acc += vsh[i][t]*wsh[o][i];
        g_s[(size_t)o*S3+s0+t]=acc;
    }
}

// ---------------- last layer: GN-apply + FiLM + p1 + GELU + p2 ----------------
__global__ void __launch_bounds__(256) gn_apply_head_k(const float* __restrict__ gg, const float* __restrict__ gb,
        int l, const float* __restrict__ w1, const float* __restrict__ b1,
        const float* __restrict__ w2, const float* __restrict__ b2, float* __restrict__ out){
    int s0 = blockIdx.x*64;
    __shared__ float vsh[64][65];
    __shared__ float red[3][4][64];
    int t = threadIdx.x&63, q = threadIdx.x>>6;
    #pragma unroll
    for(int k=0;k<16;k++){
        int c = q*16+k;
        int g = c>>3;
        float mu=g_gnf[g*2], rs=g_gnf[g*2+1];
        float xv = (g_s[(size_t)c*S3+s0+t]-mu)*rs*__ldg(&gg[c])+__ldg(&gb[c]);
        float y = gelu_f(xv);
        float sc=g_film[(l*64+c)*2], sh=g_film[(l*64+c)*2+1];
        vsh[c][t]=y*(1.f+sc)+sh;
    }
    __syncthreads();
    float a0=0.f,a1=0.f,a2=0.f;
    for(int o2=q*32;o2<q*32+32;o2++){
        float acc = __ldg(&b1[o2]);
        const float* wr = w1 + o2*64;
        #pragma unroll
        for(int i=0;i<64;i++) acc += vsh[i][t]*__ldg(&wr[i]);
        float u = gelu_f(acc);
        a0 += u*__ldg(&w2[o2]);
        a1 += u*__ldg(&w2[128+o2]);
        a2 += u*__ldg(&w2[256+o2]);
    }
    red[0][q][t]=a0; red[1][q][t]=a1; red[2][q][t]=a2;
    __syncthreads();
    if(q==0){
        #pragma unroll
        for(int j=0;j<3;j++)
            out[(size_t)j*S3+s0+t] = red[j][0][t]+red[j][1][t]+red[j][2][t]+red[j][3][t]+__ldg(&b2[j]);
    }
}

// ---------------- launch ----------------
extern "C" void kernel_launch(void* const* d_in, const int* in_sizes, int n_in,
                              void* d_out, int out_size){
    const float* x      = (const float*)d_in[0];
    const float* latent = (const float*)d_in[1];
    const float* lift_w = (const float*)d_in[2];
    const float* lift_b = (const float*)d_in[3];
    const float* sc_w1  = (const float*)d_in[4];
    const float* sc_w2  = (const float*)d_in[5];
    const float* sc_w3  = (const float*)d_in[6];
    const float* sc_w4  = (const float*)d_in[7];
    const float* conv_w = (const float*)d_in[8];
    const float* conv_b = (const float*)d_in[9];
    const float* gn_g   = (const float*)d_in[10];
    const float* gn_b   = (const float*)d_in[11];
    const float* p1_w   = (const float*)d_in[12];
    const float* p1_b   = (const float*)d_in[13];
    const float* p2_w   = (const float*)d_in[14];
    const float* p2_b   = (const float*)d_in[15];
    const float* c1_w   = (const float*)d_in[16];
    const float* c1_b   = (const float*)d_in[17];
    const float* c2_w   = (const float*)d_in[18];
    const float* c2_b   = (const float*)d_in[19];
    float* out = (float*)d_out;

    init_tables_k<<<6,256>>>();
    film1_k<<<128,256>>>(latent, c1_w, c1_b);
    film2_k<<<48,256>>>(c2_w, c2_b);
    lift_conv_k<<<4096,256>>>(x, lift_w, lift_b, conv_w, conv_b);

    const size_t WOFF = (size_t)64*64*12*12*12*2;
    for(int l=0;l<3;l++){
        fwdWH_k<<<dim3(64,64),256>>>();
        fwdD_k<<<dim3(24,64),256>>>();
        mix_k<<<dim3(108,8),256>>>(sc_w1 + l*WOFF, sc_w2 + l*WOFF,
                                   sc_w3 + l*WOFF, sc_w4 + l*WOFF);
        invD_k<<<dim3(24,64),256>>>();
        invHW_gn_k<<<dim3(64,64),256>>>();
        gn_final_k<<<1,32>>>();
        if(l<2)
            gn_apply_conv_k<<<4096,256>>>(gn_g + l*64, gn_b + l*64, l,
                                          conv_w + (l+1)*4096, conv_b + (l+1)*64);
        else
            gn_apply_head_k<<<4096,256>>>(gn_g + l*64, gn_b + l*64, l,
                                          p1_w, p1_b, p2_w, p2_b, out);
    }
}

// round 3
// speedup vs baseline: 2.4095x; 1.5081x over previous
#include <cuda_runtime.h>
#include <math.h>

#define S3 262144        // 64^3
#define NMODE 6912       // 24*24*12

// ---------------- scratch ----------------
__device__ float  g_v[64*S3];
__device__ float  g_s[64*S3];
__device__ float2 g_B[64*64*288];
__device__ float2 g_X[64*NMODE];
__device__ float2 g_Y[64*NMODE];
__device__ float  g_h1[1024];
__device__ float  g_film[384];
__device__ double g_gn[16];
__device__ float  g_gnf[16];
__device__ float2 tw_fWt[64*12];   // [w][kw]  fwd W twiddle, transposed
__device__ float2 tw_iW[12*64];    // [kw][w]  inv W twiddle * alpha/64^3
__device__ float2 tw_fDHt[64*24];  // [x][j]   fwd D/H twiddle, transposed
__device__ float2 tw_iDH[24*64];   // [j][x]   inv D/H twiddle

__device__ __forceinline__ float gelu_f(float x){
    return 0.5f*x*(1.0f + erff(x*0.7071067811865476f));
}

#define CMAC(acc, a, t) { acc.x += a.x*t.x - a.y*t.y; acc.y += a.x*t.y + a.y*t.x; }

// ---------------- tables ----------------
__global__ void init_tables_k(){
    int t = blockIdx.x*blockDim.x + threadIdx.x;
    const double w0 = 6.283185307179586476925286766559/64.0;
    if(t < 768){
        int kw = t>>6, w = t&63;
        double s,c; sincos(w0*(double)(kw*w), &s, &c);
        tw_fWt[w*12+kw] = make_float2((float)c, (float)(-s));
        double al = (kw==0 ? 1.0 : 2.0) / 262144.0;
        tw_iW[kw*64+w] = make_float2((float)(al*c), (float)(al*s));
    }
    if(t < 1536){
        int j = t>>6, x = t&63;
        int bin = (j<12) ? j : (j+40);
        double s,c; sincos(w0*(double)(bin*x), &s, &c);
        tw_fDHt[x*24+j] = make_float2((float)c, (float)(-s));
        tw_iDH[j*64+x]  = make_float2((float)c, (float)( s));
    }
    if(t < 16) g_gn[t] = 0.0;
}

// ---------------- FiLM ----------------
__global__ void film1_k(const float* __restrict__ latent, const float* __restrict__ w,
                        const float* __restrict__ b){
    int wid  = (blockIdx.x*blockDim.x + threadIdx.x) >> 5;
    int lane = threadIdx.x & 31;
    if(wid >= 1024) return;
    const float* wr = w + wid*512;
    float acc = 0.f;
    for(int k=lane;k<512;k+=32) acc += latent[k]*wr[k];
    #pragma unroll
    for(int o=16;o;o>>=1) acc += __shfl_xor_sync(0xffffffffu, acc, o);
    if(lane==0) g_h1[wid] = gelu_f(acc + b[wid]);
}
__global__ void film2_k(const float* __restrict__ w, const float* __restrict__ b){
    int wid  = (blockIdx.x*blockDim.x + threadIdx.x) >> 5;
    int lane = threadIdx.x & 31;
    if(wid >= 384) return;
    const float* wr = w + wid*1024;
    float acc = 0.f;
    for(int k=lane;k<1024;k+=32) acc += g_h1[k]*wr[k];
    #pragma unroll
    for(int o=16;o;o>>=1) acc += __shfl_xor_sync(0xffffffffu, acc, o);
    if(lane==0) g_film[wid] = acc + b[wid];
}

// ---------------- lift + conv(layer0), register-tiled ----------------
__global__ void __launch_bounds__(256) lift_conv_k(const float* __restrict__ x,
        const float* __restrict__ lw, const float* __restrict__ lb,
        const float* __restrict__ cw, const float* __restrict__ cb){
    int s0 = blockIdx.x*128;
    __shared__ float vsh[64][128];
    __shared__ float wsh[64][64];
    int s = threadIdx.x & 127, chalf = threadIdx.x >> 7;
    float x0 = __ldg(&x[s0+s]),        x1 = __ldg(&x[S3+s0+s]);
    float x2 = __ldg(&x[2*S3+s0+s]),   x3 = __ldg(&x[3*S3+s0+s]);
    for(int i=threadIdx.x;i<4096;i+=256) wsh[i>>6][i&63] = cw[i];
    #pragma unroll
    for(int i=0;i<32;i++){
        int cc = i*2 + chalf;
        float v = __ldg(&lb[cc]) + __ldg(&lw[cc*4+0])*x0 + __ldg(&lw[cc*4+1])*x1
                                 + __ldg(&lw[cc*4+2])*x2 + __ldg(&lw[cc*4+3])*x3;
        vsh[cc][s] = v;
        g_v[(size_t)cc*S3 + s0 + s] = v;
    }
    __syncthreads();
    int o0 = (threadIdx.x>>5)*8, si = (threadIdx.x&31)*4;
    float acc[8][4];
    #pragma unroll
    for(int a=0;a<8;a++){ acc[a][0]=0.f;acc[a][1]=0.f;acc[a][2]=0.f;acc[a][3]=0.f; }
    for(int k=0;k<64;k++){
        float4 v4 = *(const float4*)&vsh[k][si];
        #pragma unroll
        for(int oi=0;oi<8;oi++){
            float wv = wsh[o0+oi][k];
            acc[oi][0] += wv*v4.x; acc[oi][1] += wv*v4.y;
            acc[oi][2] += wv*v4.z; acc[oi][3] += wv*v4.w;
        }
    }
    #pragma unroll
    for(int oi=0;oi<8;oi++){
        float bb = __ldg(&cb[o0+oi]);
        *(float4*)&g_s[(size_t)(o0+oi)*S3 + s0 + si] =
            make_float4(acc[oi][0]+bb, acc[oi][1]+bb, acc[oi][2]+bb, acc[oi][3]+bb);
    }
}

// ---------------- fused forward DFT: W then H ----------------
__global__ void __launch_bounds__(128) fwdWH_k(){
    int d = blockIdx.x, c = blockIdx.y;
    __shared__ float vsh[64][65];
    __shared__ __align__(16) float2 twWt[64][12];
    __shared__ float2 Ash[12][64];
    __shared__ float2 twHt[64][24];
    const float4* src = (const float4*)(g_v + (size_t)(c*64+d)*4096);
    for(int i=threadIdx.x;i<1024;i+=128){
        float4 v4 = src[i];
        int h = i>>4, w4 = (i&15)*4;
        vsh[h][w4]=v4.x; vsh[h][w4+1]=v4.y; vsh[h][w4+2]=v4.z; vsh[h][w4+3]=v4.w;
    }
    for(int i=threadIdx.x;i<768;i+=128)  ((float2*)twWt)[i] = tw_fWt[i];
    for(int i=threadIdx.x;i<1536;i+=128) ((float2*)twHt)[i] = tw_fDHt[i];
    __syncthreads();
    {
        int h = threadIdx.x & 63, kw0 = (threadIdx.x>>6)*6;
        float2 a0={0,0},a1={0,0},a2={0,0},a3={0,0},a4={0,0},a5={0,0};
        for(int w=0;w<64;w++){
            float v = vsh[h][w];
            const float4* tp = (const float4*)(&twWt[w][kw0]);
            float4 t0 = tp[0], t1 = tp[1], t2 = tp[2];
            a0.x += v*t0.x; a0.y += v*t0.y; a1.x += v*t0.z; a1.y += v*t0.w;
            a2.x += v*t1.x; a2.y += v*t1.y; a3.x += v*t1.z; a3.y += v*t1.w;
            a4.x += v*t2.x; a4.y += v*t2.y; a5.x += v*t2.z; a5.y += v*t2.w;
        }
        Ash[kw0+0][h]=a0; Ash[kw0+1][h]=a1; Ash[kw0+2][h]=a2;
        Ash[kw0+3][h]=a3; Ash[kw0+4][h]=a4; Ash[kw0+5][h]=a5;
    }
    __syncthreads();
    if(threadIdx.x < 96){
        int kw = threadIdx.x % 12, jh0 = (threadIdx.x/12)*3;
        float2 b0={0,0},b1={0,0},b2={0,0};
        for(int h=0;h<64;h++){
            float2 a = Ash[kw][h];
            float2 t0 = twHt[h][jh0], t1 = twHt[h][jh0+1], t2 = twHt[h][jh0+2];
            CMAC(b0,a,t0); CMAC(b1,a,t1); CMAC(b2,a,t2);
        }
        float2* dst = g_B + (size_t)(c*64+d)*288;
        dst[jh0*12+kw]=b0; dst[(jh0+1)*12+kw]=b1; dst[(jh0+2)*12+kw]=b2;
    }
}

// ---------------- forward DFT over D ----------------
__global__ void __launch_bounds__(128) fwdD_k(){
    int jh = blockIdx.x, c = blockIdx.y;
    __shared__ float2 Bsh[64][12];   // [d][kw]
    __shared__ float2 twDt[64][24];  // [d][jd]
    for(int i=threadIdx.x;i<768;i+=128){
        int d = i/12, kw = i - d*12;
        Bsh[d][kw] = g_B[(size_t)(c*64+d)*288 + jh*12 + kw];
    }
    for(int i=threadIdx.x;i<1536;i+=128) ((float2*)twDt)[i] = tw_fDHt[i];
    __syncthreads();
    if(threadIdx.x < 96){
        int kw = threadIdx.x % 12, jd0 = (threadIdx.x/12)*3;
        float2 b0={0,0},b1={0,0},b2={0,0};
        for(int d=0;d<64;d++){
            float2 a = Bsh[d][kw];
            float2 t0 = twDt[d][jd0], t1 = twDt[d][jd0+1], t2 = twDt[d][jd0+2];
            CMAC(b0,a,t0); CMAC(b1,a,t1); CMAC(b2,a,t2);
        }
        g_X[(size_t)c*NMODE + ((jd0  )*24+jh)*12 + kw] = b0;
        g_X[(size_t)c*NMODE + ((jd0+1)*24+jh)*12 + kw] = b1;
        g_X[(size_t)c*NMODE + ((jd0+2)*24+jh)*12 + kw] = b2;
    }
}

// ---------------- per-mode channel mix ----------------
__global__ void __launch_bounds__(256) mix_k(const float* __restrict__ w1, const float* __restrict__ w2,
                                             const float* __restrict__ w3, const float* __restrict__ w4){
    int m0 = blockIdx.x*64;
    __shared__ float2 xs[64][64];
    int tx = threadIdx.x & 63, ty = threadIdx.x >> 6;
    for(int i=ty;i<64;i+=4) xs[i][tx] = g_X[i*NMODE + m0 + tx];
    __syncthreads();
    int mode = m0 + tx;
    int jd = mode/288; int r = mode - jd*288; int jh = r/12; int kw = r - jh*12;
    const float* wbase = (jd<12) ? (jh<12 ? w1 : w3) : (jh<12 ? w2 : w4);
    int cmode = ((jd%12)*12 + (jh%12))*12 + kw;
    const float2* W = (const float2*)wbase + cmode;
    int o0 = blockIdx.y*8 + ty*2;
    const float2* W0 = W + (size_t)o0*1728;
    const float2* W1 = W0 + 1728;
    float re0=0.f,im0=0.f,re1=0.f,im1=0.f;
    #pragma unroll 4
    for(int i=0;i<64;i++){
        float2 xv = xs[i][tx];
        float2 wa = __ldg(W0 + (size_t)i*110592);
        float2 wb = __ldg(W1 + (size_t)i*110592);
        re0 += xv.x*wa.x - xv.y*wa.y; im0 += xv.x*wa.y + xv.y*wa.x;
        re1 += xv.x*wb.x - xv.y*wb.y; im1 += xv.x*wb.y + xv.y*wb.x;
    }
    g_Y[(size_t)o0*NMODE + mode]     = make_float2(re0,im0);
    g_Y[(size_t)(o0+1)*NMODE + mode] = make_float2(re1,im1);
}

// ---------------- inverse DFT over D ----------------
__global__ void __launch_bounds__(128) invD_k(){
    int jh = blockIdx.x, c = blockIdx.y;
    __shared__ __align__(16) float2 Ysh[24][12];
    __shared__ float2 twD[24][64];
    for(int i=threadIdx.x;i<288;i+=128){
        int jd = i/12, kw = i - jd*12;
        Ysh[jd][kw] = g_Y[(size_t)c*NMODE + (jd*24+jh)*12 + kw];
    }
    for(int i=threadIdx.x;i<1536;i+=128) ((float2*)twD)[i] = tw_iDH[i];
    __syncthreads();
    int d = threadIdx.x & 63, kw0 = (threadIdx.x>>6)*6;
    float2 a0={0,0},a1={0,0},a2={0,0},a3={0,0},a4={0,0},a5={0,0};
    for(int jd=0;jd<24;jd++){
        float2 t = twD[jd][d];
        const float4* yp = (const float4*)(&Ysh[jd][kw0]);
        float4 y0 = yp[0], y1 = yp[1], y2 = yp[2];
        float2 v;
        v = make_float2(y0.x,y0.y); CMAC(a0,v,t);
        v = make_float2(y0.z,y0.w); CMAC(a1,v,t);
        v = make_float2(y1.x,y1.y); CMAC(a2,v,t);
        v = make_float2(y1.z,y1.w); CMAC(a3,v,t);
        v = make_float2(y2.x,y2.y); CMAC(a4,v,t);
        v = make_float2(y2.z,y2.w); CMAC(a5,v,t);
    }
    float2* dst = g_B + (size_t)(c*64+d)*288 + jh*12 + kw0;
    dst[0]=a0; dst[1]=a1; dst[2]=a2; dst[3]=a3; dst[4]=a4; dst[5]=a5;
}

// ---------------- fused inverse H + W + residual add + GN stats ----------------
__global__ void __launch_bounds__(128) invHW_gn_k(){
    int d = blockIdx.x, c = blockIdx.y;
    __shared__ __align__(16) float2 Bsh[288];
    __shared__ float2 Ash[12][64];
    __shared__ float2 twH[24][64];
    __shared__ float2 twW[12][64];
    __shared__ float redS[4], redQ[4];
    const float2* src = g_B + (size_t)(c*64+d)*288;
    for(int i=threadIdx.x;i<288;i+=128)  Bsh[i] = src[i];
    for(int i=threadIdx.x;i<1536;i+=128) ((float2*)twH)[i] = tw_iDH[i];
    for(int i=threadIdx.x;i<768;i+=128)  ((float2*)twW)[i] = tw_iW[i];
    __syncthreads();
    {
        int h = threadIdx.x & 63, kw0 = (threadIdx.x>>6)*6;
        float2 a0={0,0},a1={0,0},a2={0,0},a3={0,0},a4={0,0},a5={0,0};
        for(int jh=0;jh<24;jh++){
            float2 t = twH[jh][h];
            const float4* bp = (const float4*)(&Bsh[jh*12+kw0]);
            float4 b0 = bp[0], b1 = bp[1], b2 = bp[2];
            float2 v;
            v = make_float2(b0.x,b0.y); CMAC(a0,v,t);
            v = make_float2(b0.z,b0.w); CMAC(a1,v,t);
            v = make_float2(b1.x,b1.y); CMAC(a2,v,t);
            v = make_float2(b1.z,b1.w); CMAC(a3,v,t);
            v = make_float2(b2.x,b2.y); CMAC(a4,v,t);
            v = make_float2(b2.z,b2.w); CMAC(a5,v,t);
        }
        Ash[kw0+0][h]=a0; Ash[kw0+1][h]=a1; Ash[kw0+2][h]=a2;
        Ash[kw0+3][h]=a3; Ash[kw0+4][h]=a4; Ash[kw0+5][h]=a5;
    }
    __syncthreads();
    int wp = threadIdx.x & 31, hg = threadIdx.x >> 5;
    float2 tA[12], tB[12];
    #pragma unroll
    for(int kw=0;kw<12;kw++){ tA[kw]=twW[kw][wp*2]; tB[kw]=twW[kw][wp*2+1]; }
    float ssum=0.f, sq=0.f;
    float2* srow = (float2*)(g_s + (size_t)c*S3 + d*4096);
    for(int h=hg*16; h<hg*16+16; h++){
        float r0=0.f, r1=0.f;
        #pragma unroll
        for(int kw=0;kw<12;kw++){
            float2 a = Ash[kw][h];
            r0 += a.x*tA[kw].x - a.y*tA[kw].y;
            r1 += a.x*tB[kw].x - a.y*tB[kw].y;
        }
        float2 sv = srow[h*32+wp];
        sv.x += r0; sv.y += r1;
        srow[h*32+wp] = sv;
        ssum += sv.x + sv.y; sq += sv.x*sv.x + sv.y*sv.y;
    }
    #pragma unroll
    for(int o=16;o;o>>=1){ ssum += __shfl_xor_sync(0xffffffffu,ssum,o);
                           sq   += __shfl_xor_sync(0xffffffffu,sq,o); }
    if(wp==0){ redS[hg]=ssum; redQ[hg]=sq; }
    __syncthreads();
    if(threadIdx.x==0){
        float S = redS[0]+redS[1]+redS[2]+redS[3];
        float Q = redQ[0]+redQ[1]+redQ[2]+redQ[3];
        int g = c>>3;
        atomicAdd(&g_gn[g*2],   (double)S);
        atomicAdd(&g_gn[g*2+1], (double)Q);
    }
}

__global__ void gn_final_k(){
    int g = threadIdx.x;
    float mu_f=0.f, rs_f=0.f;
    if(g<8){
        double n = 8.0*(double)S3;
        double mu = g_gn[g*2]/n;
        double var = g_gn[g*2+1]/n - mu*mu;
        mu_f = (float)mu; rs_f = (float)(1.0/sqrt(var + 1e-5));
    }
    __syncthreads();
    if(g<8){ g_gnf[g*2]=mu_f; g_gnf[g*2+1]=rs_f; }
    if(g<16) g_gn[g]=0.0;
}

// ---------------- GN-apply + GELU + FiLM + conv(next layer), register-tiled ----------------
__global__ void __launch_bounds__(256) gn_apply_conv_k(const float* __restrict__ gg, const float* __restrict__ gb,
        int l, const float* __restrict__ cw, const float* __restrict__ cb){
    int s0 = blockIdx.x*128;
    __shared__ float vsh[64][128];
    __shared__ float wsh[64][64];
    int s = threadIdx.x & 127, chalf = threadIdx.x >> 7;
    for(int i=threadIdx.x;i<4096;i+=256) wsh[i>>6][i&63] = cw[i];
    #pragma unroll
    for(int i=0;i<32;i++){
        int cc = i*2 + chalf;
        int g = cc>>3;
        float xv = (g_s[(size_t)cc*S3+s0+s]-g_gnf[g*2])*g_gnf[g*2+1]*__ldg(&gg[cc]) + __ldg(&gb[cc]);
        float y = gelu_f(xv);
        float v = y*(1.f+g_film[(l*64+cc)*2]) + g_film[(l*64+cc)*2+1];
        vsh[cc][s] = v;
        g_v[(size_t)cc*S3+s0+s] = v;
    }
    __syncthreads();
    int o0 = (threadIdx.x>>5)*8, si = (threadIdx.x&31)*4;
    float acc[8][4];
    #pragma unroll
    for(int a=0;a<8;a++){ acc[a][0]=0.f;acc[a][1]=0.f;acc[a][2]=0.f;acc[a][3]=0.f; }
    for(int k=0;k<64;k++){
        float4 v4 = *(const float4*)&vsh[k][si];
        #pragma unroll
        for(int oi=0;oi<8;oi++){
            float wv = wsh[o0+oi][k];
            acc[oi][0] += wv*v4.x; acc[oi][1] += wv*v4.y;
            acc[oi][2] += wv*v4.z; acc[oi][3] += wv*v4.w;
        }
    }
    #pragma unroll
    for(int oi=0;oi<8;oi++){
        float bb = __ldg(&cb[o0+oi]);
        *(float4*)&g_s[(size_t)(o0+oi)*S3 + s0 + si] =
            make_float4(acc[oi][0]+bb, acc[oi][1]+bb, acc[oi][2]+bb, acc[oi][3]+bb);
    }
}

// ---------------- last layer: GN-apply + FiLM + p1 + GELU + p2, register-tiled ----------------
__global__ void __launch_bounds__(256) gn_apply_head_k(const float* __restrict__ gg, const float* __restrict__ gb,
        int l, const float* __restrict__ w1, const float* __restrict__ b1,
        const float* __restrict__ w2, const float* __restrict__ b2, float* __restrict__ out){
    int s0 = blockIdx.x*64;
    __shared__ float vsh[64][64];
    __shared__ float wsh[64][64];
    __shared__ float w2s[3][128];
    __shared__ float red[16][3][64];
    int s = threadIdx.x & 63, cq = threadIdx.x >> 6;
    for(int i=threadIdx.x;i<384;i+=256){ int j=i>>7, o=i&127; w2s[j][o]=w2[j*128+o]; }
    #pragma unroll
    for(int i=0;i<16;i++){
        int cc = i*4 + cq;
        int g = cc>>3;
        float xv = (g_s[(size_t)cc*S3+s0+s]-g_gnf[g*2])*g_gnf[g*2+1]*__ldg(&gg[cc]) + __ldg(&gb[cc]);
        float y = gelu_f(xv);
        vsh[cc][s] = y*(1.f+g_film[(l*64+cc)*2]) + g_film[(l*64+cc)*2+1];
    }
    int og = threadIdx.x >> 4, sg = threadIdx.x & 15;
    int o0 = og*4, si = sg*4;
    float p[3][4];
    #pragma unroll
    for(int j=0;j<3;j++){ p[j][0]=0.f;p[j][1]=0.f;p[j][2]=0.f;p[j][3]=0.f; }
    for(int half=0; half<2; half++){
        __syncthreads();
        for(int i=threadIdx.x;i<4096;i+=256){ int o=i>>6,k=i&63; wsh[o][k]=w1[(half*64+o)*64+k]; }
        __syncthreads();
        float acc[4][4];
        #pragma unroll
        for(int a=0;a<4;a++){ acc[a][0]=0.f;acc[a][1]=0.f;acc[a][2]=0.f;acc[a][3]=0.f; }
        for(int k=0;k<64;k++){
            float4 v4 = *(const float4*)&vsh[k][si];
            #pragma unroll
            for(int oi=0;oi<4;oi++){
                float wv = wsh[o0+oi][k];
                acc[oi][0] += wv*v4.x; acc[oi][1] += wv*v4.y;
                acc[oi][2] += wv*v4.z; acc[oi][3] += wv*v4.w;
            }
        }
        #pragma unroll
        for(int oi=0;oi<4;oi++){
            int o = half*64 + o0 + oi;
            float bb = __ldg(&b1[o]);
            #pragma unroll
            for(int sx=0;sx<4;sx++){
                float u = gelu_f(acc[oi][sx] + bb);
                p[0][sx] += u*w2s[0][o];
                p[1][sx] += u*w2s[1][o];
                p[2][sx] += u*w2s[2][o];
            }
        }
    }
    #pragma unroll
    for(int j=0;j<3;j++){
        red[og][j][si+0]=p[j][0]; red[og][j][si+1]=p[j][1];
        red[og][j][si+2]=p[j][2]; red[og][j][si+3]=p[j][3];
    }
    __syncthreads();
    if(threadIdx.x < 64){
        int ss = threadIdx.x;
        #pragma unroll
        for(int j=0;j<3;j++){
            float acc = __ldg(&b2[j]);
            #pragma unroll
            for(int gq=0;gq<16;gq++) acc += red[gq][j][ss];
            out[(size_t)j*S3 + s0 + ss] = acc;
        }
    }
}

// ---------------- launch ----------------
extern "C" void kernel_launch(void* const* d_in, const int* in_sizes, int n_in,
                              void* d_out, int out_size){
    const float* x      = (const float*)d_in[0];
    const float* latent = (const float*)d_in[1];
    const float* lift_w = (const float*)d_in[2];
    const float* lift_b = (const float*)d_in[3];
    const float* sc_w1  = (const float*)d_in[4];
    const float* sc_w2  = (const float*)d_in[5];
    const float* sc_w3  = (const float*)d_in[6];
    const float* sc_w4  = (const float*)d_in[7];
    const float* conv_w = (const float*)d_in[8];
    const float* conv_b = (const float*)d_in[9];
    const float* gn_g   = (const float*)d_in[10];
    const float* gn_b   = (const float*)d_in[11];
    const float* p1_w   = (const float*)d_in[12];
    const float* p1_b   = (const float*)d_in[13];
    const float* p2_w   = (const float*)d_in[14];
    const float* p2_b   = (const float*)d_in[15];
    const float* c1_w   = (const float*)d_in[16];
    const float* c1_b   = (const float*)d_in[17];
    const float* c2_w   = (const float*)d_in[18];
    const float* c2_b   = (const float*)d_in[19];
    float* out = (float*)d_out;

    init_tables_k<<<6,256>>>();
    film1_k<<<128,256>>>(latent, c1_w, c1_b);
    film2_k<<<48,256>>>(c2_w, c2_b);
    lift_conv_k<<<2048,256>>>(x, lift_w, lift_b, conv_w, conv_b);

    const size_t WOFF = (size_t)64*64*12*12*12*2;
    for(int l=0;l<3;l++){
        fwdWH_k<<<dim3(64,64),128>>>();
        fwdD_k<<<dim3(24,64),128>>>();
        mix_k<<<dim3(108,8),256>>>(sc_w1 + l*WOFF, sc_w2 + l*WOFF,
                                   sc_w3 + l*WOFF, sc_w4 + l*WOFF);
        invD_k<<<dim3(24,64),128>>>();
        invHW_gn_k<<<dim3(64,64),128>>>();
        gn_final_k<<<1,32>>>();
        if(l<2)
            gn_apply_conv_k<<<2048,256>>>(gn_g + l*64, gn_b + l*64, l,
                                          conv_w + (l+1)*4096, conv_b + (l+1)*64);
        else
            gn_apply_head_k<<<4096,256>>>(gn_g + l*64, gn_b + l*64, l,
                                          p1_w, p1_b, p2_w, p2_b, out);
    }
}

// round 4
// speedup vs baseline: 2.4613x; 1.0215x over previous
#include <cuda_runtime.h>
#include <math.h>

#define S3 262144        // 64^3
#define NMODE 6912       // 4 corners * 1728

// ---------------- scratch ----------------
__device__ float  g_v[64*S3];
__device__ float  g_s[64*S3];
__device__ float2 g_B[64*64*288];
__device__ float2 g_X[64*NMODE];   // corner-major: c*NMODE + corner*1728 + cmode
__device__ float2 g_Y[64*NMODE];
__device__ float  g_h1[1024];
__device__ float  g_film[384];
__device__ double g_gn[16];
__device__ float  g_gnf[16];
__device__ float2 tw_fWt[64*12];   // [w][kw]  fwd W twiddle, transposed
__device__ float2 tw_iW[12*64];    // [kw][w]  inv W twiddle * alpha/64^3
__device__ float2 tw_fDHt[64*24];  // [x][j]   fwd D/H twiddle, transposed
__device__ float2 tw_iDH[24*64];   // [j][x]   inv D/H twiddle

__device__ __forceinline__ float gelu_f(float x){
    return 0.5f*x*(1.0f + erff(x*0.7071067811865476f));
}

#define CMAC(acc, a, t) { acc.x += a.x*t.x - a.y*t.y; acc.y += a.x*t.y + a.y*t.x; }

// ---------------- tables ----------------
__global__ void init_tables_k(){
    int t = blockIdx.x*blockDim.x + threadIdx.x;
    const double w0 = 6.283185307179586476925286766559/64.0;
    if(t < 768){
        int kw = t>>6, w = t&63;
        double s,c; sincos(w0*(double)(kw*w), &s, &c);
        tw_fWt[w*12+kw] = make_float2((float)c, (float)(-s));
        double al = (kw==0 ? 1.0 : 2.0) / 262144.0;
        tw_iW[kw*64+w] = make_float2((float)(al*c), (float)(al*s));
    }
    if(t < 1536){
        int j = t>>6, x = t&63;
        int bin = (j<12) ? j : (j+40);
        double s,c; sincos(w0*(double)(bin*x), &s, &c);
        tw_fDHt[x*24+j] = make_float2((float)c, (float)(-s));
        tw_iDH[j*64+x]  = make_float2((float)c, (float)( s));
    }
    if(t < 16) g_gn[t] = 0.0;
}

// ---------------- FiLM ----------------
__global__ void film1_k(const float* __restrict__ latent, const float* __restrict__ w,
                        const float* __restrict__ b){
    int wid  = (blockIdx.x*blockDim.x + threadIdx.x) >> 5;
    int lane = threadIdx.x & 31;
    if(wid >= 1024) return;
    const float* wr = w + wid*512;
    float acc = 0.f;
    for(int k=lane;k<512;k+=32) acc += latent[k]*wr[k];
    #pragma unroll
    for(int o=16;o;o>>=1) acc += __shfl_xor_sync(0xffffffffu, acc, o);
    if(lane==0) g_h1[wid] = gelu_f(acc + b[wid]);
}
__global__ void film2_k(const float* __restrict__ w, const float* __restrict__ b){
    int wid  = (blockIdx.x*blockDim.x + threadIdx.x) >> 5;
    int lane = threadIdx.x & 31;
    if(wid >= 384) return;
    const float* wr = w + wid*1024;
    float acc = 0.f;
    for(int k=lane;k<1024;k+=32) acc += g_h1[k]*wr[k];
    #pragma unroll
    for(int o=16;o;o>>=1) acc += __shfl_xor_sync(0xffffffffu, acc, o);
    if(lane==0) g_film[wid] = acc + b[wid];
}

// ---------------- lift + conv(layer0), register-tiled, transposed weights ----------------
__global__ void __launch_bounds__(256) lift_conv_k(const float* __restrict__ x,
        const float* __restrict__ lw, const float* __restrict__ lb,
        const float* __restrict__ cw, const float* __restrict__ cb){
    int s0 = blockIdx.x*128;
    __shared__ float vsh[64][128];
    __shared__ float wshT[64][68];
    int s = threadIdx.x & 127, chalf = threadIdx.x >> 7;
    float x0 = __ldg(&x[s0+s]),        x1 = __ldg(&x[S3+s0+s]);
    float x2 = __ldg(&x[2*S3+s0+s]),   x3 = __ldg(&x[3*S3+s0+s]);
    for(int i=threadIdx.x;i<4096;i+=256) wshT[i&63][i>>6] = cw[i];
    #pragma unroll
    for(int i=0;i<32;i++){
        int cc = i*2 + chalf;
        float v = __ldg(&lb[cc]) + __ldg(&lw[cc*4+0])*x0 + __ldg(&lw[cc*4+1])*x1
                                 + __ldg(&lw[cc*4+2])*x2 + __ldg(&lw[cc*4+3])*x3;
        vsh[cc][s] = v;
        g_v[(size_t)cc*S3 + s0 + s] = v;
    }
    __syncthreads();
    int o0 = (threadIdx.x>>5)*8, si = (threadIdx.x&31)*4;
    float acc[8][4];
    #pragma unroll
    for(int a=0;a<8;a++){ acc[a][0]=0.f;acc[a][1]=0.f;acc[a][2]=0.f;acc[a][3]=0.f; }
    for(int k=0;k<64;k++){
        float4 v4 = *(const float4*)&vsh[k][si];
        float4 wa = *(const float4*)&wshT[k][o0];
        float4 wb = *(const float4*)&wshT[k][o0+4];
        acc[0][0]+=wa.x*v4.x; acc[0][1]+=wa.x*v4.y; acc[0][2]+=wa.x*v4.z; acc[0][3]+=wa.x*v4.w;
        acc[1][0]+=wa.y*v4.x; acc[1][1]+=wa.y*v4.y; acc[1][2]+=wa.y*v4.z; acc[1][3]+=wa.y*v4.w;
        acc[2][0]+=wa.z*v4.x; acc[2][1]+=wa.z*v4.y; acc[2][2]+=wa.z*v4.z; acc[2][3]+=wa.z*v4.w;
        acc[3][0]+=wa.w*v4.x; acc[3][1]+=wa.w*v4.y; acc[3][2]+=wa.w*v4.z; acc[3][3]+=wa.w*v4.w;
        acc[4][0]+=wb.x*v4.x; acc[4][1]+=wb.x*v4.y; acc[4][2]+=wb.x*v4.z; acc[4][3]+=wb.x*v4.w;
        acc[5][0]+=wb.y*v4.x; acc[5][1]+=wb.y*v4.y; acc[5][2]+=wb.y*v4.z; acc[5][3]+=wb.y*v4.w;
        acc[6][0]+=wb.z*v4.x; acc[6][1]+=wb.z*v4.y; acc[6][2]+=wb.z*v4.z; acc[6][3]+=wb.z*v4.w;
        acc[7][0]+=wb.w*v4.x; acc[7][1]+=wb.w*v4.y; acc[7][2]+=wb.w*v4.z; acc[7][3]+=wb.w*v4.w;
    }
    #pragma unroll
    for(int oi=0;oi<8;oi++){
        float bb = __ldg(&cb[o0+oi]);
        *(float4*)&g_s[(size_t)(o0+oi)*S3 + s0 + si] =
            make_float4(acc[oi][0]+bb, acc[oi][1]+bb, acc[oi][2]+bb, acc[oi][3]+bb);
    }
}

// ---------------- fused forward DFT: W then H ----------------
__global__ void __launch_bounds__(128) fwdWH_k(){
    int d = blockIdx.x, c = blockIdx.y;
    __shared__ float vsh[64][65];
    __shared__ __align__(16) float2 twWt[64][12];
    __shared__ float2 Ash[12][64];
    __shared__ float2 twHt[64][24];
    const float4* src = (const float4*)(g_v + (size_t)(c*64+d)*4096);
    for(int i=threadIdx.x;i<1024;i+=128){
        float4 v4 = src[i];
        int h = i>>4, w4 = (i&15)*4;
        vsh[h][w4]=v4.x; vsh[h][w4+1]=v4.y; vsh[h][w4+2]=v4.z; vsh[h][w4+3]=v4.w;
    }
    for(int i=threadIdx.x;i<768;i+=128)  ((float2*)twWt)[i] = tw_fWt[i];
    for(int i=threadIdx.x;i<1536;i+=128) ((float2*)twHt)[i] = tw_fDHt[i];
    __syncthreads();
    {
        int h = threadIdx.x & 63, kw0 = (threadIdx.x>>6)*6;
        float2 a0={0,0},a1={0,0},a2={0,0},a3={0,0},a4={0,0},a5={0,0};
        for(int w=0;w<64;w++){
            float v = vsh[h][w];
            const float4* tp = (const float4*)(&twWt[w][kw0]);
            float4 t0 = tp[0], t1 = tp[1], t2 = tp[2];
            a0.x += v*t0.x; a0.y += v*t0.y; a1.x += v*t0.z; a1.y += v*t0.w;
            a2.x += v*t1.x; a2.y += v*t1.y; a3.x += v*t1.z; a3.y += v*t1.w;
            a4.x += v*t2.x; a4.y += v*t2.y; a5.x += v*t2.z; a5.y += v*t2.w;
        }
        Ash[kw0+0][h]=a0; Ash[kw0+1][h]=a1; Ash[kw0+2][h]=a2;
        Ash[kw0+3][h]=a3; Ash[kw0+4][h]=a4; Ash[kw0+5][h]=a5;
    }
    __syncthreads();
    if(threadIdx.x < 96){
        int kw = threadIdx.x % 12, jh0 = (threadIdx.x/12)*3;
        float2 b0={0,0},b1={0,0},b2={0,0};
        for(int h=0;h<64;h++){
            float2 a = Ash[kw][h];
            float2 t0 = twHt[h][jh0], t1 = twHt[h][jh0+1], t2 = twHt[h][jh0+2];
            CMAC(b0,a,t0); CMAC(b1,a,t1); CMAC(b2,a,t2);
        }
        float2* dst = g_B + (size_t)(c*64+d)*288;
        dst[jh0*12+kw]=b0; dst[(jh0+1)*12+kw]=b1; dst[(jh0+2)*12+kw]=b2;
    }
}

// ---------------- forward DFT over D (stores corner-major) ----------------
__global__ void __launch_bounds__(128) fwdD_k(){
    int jh = blockIdx.x, c = blockIdx.y;
    __shared__ float2 Bsh[64][12];
    __shared__ float2 twDt[64][24];
    for(int i=threadIdx.x;i<768;i+=128){
        int d = i/12, kw = i - d*12;
        Bsh[d][kw] = g_B[(size_t)(c*64+d)*288 + jh*12 + kw];
    }
    for(int i=threadIdx.x;i<1536;i+=128) ((float2*)twDt)[i] = tw_fDHt[i];
    __syncthreads();
    if(threadIdx.x < 96){
        int kw = threadIdx.x % 12, jd0 = (threadIdx.x/12)*3;
        float2 b0={0,0},b1={0,0},b2={0,0};
        for(int d=0;d<64;d++){
            float2 a = Bsh[d][kw];
            float2 t0 = twDt[d][jd0], t1 = twDt[d][jd0+1], t2 = twDt[d][jd0+2];
            CMAC(b0,a,t0); CMAC(b1,a,t1); CMAC(b2,a,t2);
        }
        int jhm = jh % 12, cbase = (jh>=12) ? 2 : 0;
        #pragma unroll
        for(int r=0;r<3;r++){
            int jd = jd0 + r;
            int corner = cbase + (jd>=12 ? 1 : 0);
            int cmode = ((jd%12)*12 + jhm)*12 + kw;
            float2 b = (r==0)?b0:(r==1)?b1:b2;
            g_X[(size_t)c*NMODE + corner*1728 + cmode] = b;
        }
    }
}

// ---------------- per-mode channel mix: float4 streaming ----------------
__global__ void __launch_bounds__(256) mix_k(const float* __restrict__ w1, const float* __restrict__ w2,
                                             const float* __restrict__ w3, const float* __restrict__ w4){
    int corner = blockIdx.x / 27;
    int c0 = (blockIdx.x - corner*27) * 64;
    const float* wbase = (corner==0)?w1:(corner==1)?w2:(corner==2)?w3:w4;
    __shared__ float2 xs[64][64];
    int tx = threadIdx.x & 31, ty = threadIdx.x >> 5;
    for(int i=ty; i<64; i+=8)
        ((float4*)xs[i])[tx] = *(const float4*)(&g_X[(size_t)i*NMODE + corner*1728 + c0 + tx*2]);
    __syncthreads();
    int o = blockIdx.y*8 + ty;
    const float* Wp = wbase + ((size_t)o*1728 + c0 + tx*2)*2;
    float re0=0.f,im0=0.f,re1=0.f,im1=0.f;
    #pragma unroll 8
    for(int i=0;i<64;i++){
        float4 wv = *(const float4*)(Wp + (size_t)i*221184);   // i*64*1728*2 floats
        float4 xx = ((const float4*)xs[i])[tx];
        re0 += xx.x*wv.x - xx.y*wv.y; im0 += xx.x*wv.y + xx.y*wv.x;
        re1 += xx.z*wv.z - xx.w*wv.w; im1 += xx.z*wv.w + xx.w*wv.z;
    }
    *(float4*)(&g_Y[(size_t)o*NMODE + corner*1728 + c0 + tx*2]) = make_float4(re0,im0,re1,im1);
}

// ---------------- inverse DFT over D (reads corner-major) ----------------
__global__ void __launch_bounds__(128) invD_k(){
    int jh = blockIdx.x, c = blockIdx.y;
    __shared__ __align__(16) float2 Ysh[24][12];
    __shared__ float2 twD[24][64];
    int jhm = jh % 12, cbase = (jh>=12) ? 2 : 0;
    for(int i=threadIdx.x;i<288;i+=128){
        int jd = i/12, kw = i - jd*12;
        int corner = cbase + (jd>=12 ? 1 : 0);
        int cmode = ((jd%12)*12 + jhm)*12 + kw;
        Ysh[jd][kw] = g_Y[(size_t)c*NMODE + corner*1728 + cmode];
    }
    for(int i=threadIdx.x;i<1536;i+=128) ((float2*)twD)[i] = tw_iDH[i];
    __syncthreads();
    int d = threadIdx.x & 63, kw0 = (threadIdx.x>>6)*6;
    float2 a0={0,0},a1={0,0},a2={0,0},a3={0,0},a4={0,0},a5={0,0};
    for(int jd=0;jd<24;jd++){
        float2 t = twD[jd][d];
        const float4* yp = (const float4*)(&Ysh[jd][kw0]);
        float4 y0 = yp[0], y1 = yp[1], y2 = yp[2];
        float2 v;
        v = make_float2(y0.x,y0.y); CMAC(a0,v,t);
        v = make_float2(y0.z,y0.w); CMAC(a1,v,t);
        v = make_float2(y1.x,y1.y); CMAC(a2,v,t);
        v = make_float2(y1.z,y1.w); CMAC(a3,v,t);
        v = make_float2(y2.x,y2.y); CMAC(a4,v,t);
        v = make_float2(y2.z,y2.w); CMAC(a5,v,t);
    }
    float2* dst = g_B + (size_t)(c*64+d)*288 + jh*12 + kw0;
    dst[0]=a0; dst[1]=a1; dst[2]=a2; dst[3]=a3; dst[4]=a4; dst[5]=a5;
}

// ---------------- fused inverse H + W + residual add + GN stats ----------------
__global__ void __launch_bounds__(128) invHW_gn_k(){
    int d = blockIdx.x, c = blockIdx.y;
    __shared__ __align__(16) float2 Bsh[288];
    __shared__ float2 Ash[12][64];
    __shared__ float2 twH[24][64];
    __shared__ float2 twW[12][64];
    __shared__ float redS[4], redQ[4];
    const float2* src = g_B + (size_t)(c*64+d)*288;
    for(int i=threadIdx.x;i<288;i+=128)  Bsh[i] = src[i];
    for(int i=threadIdx.x;i<1536;i+=128) ((float2*)twH)[i] = tw_iDH[i];
    for(int i=threadIdx.x;i<768;i+=128)  ((float2*)twW)[i] = tw_iW[i];
    __syncthreads();
    {
        int h = threadIdx.x & 63, kw0 = (threadIdx.x>>6)*6;
        float2 a0={0,0},a1={0,0},a2={0,0},a3={0,0},a4={0,0},a5={0,0};
        for(int jh=0;jh<24;jh++){
            float2 t = twH[jh][h];
            const float4* bp = (const float4*)(&Bsh[jh*12+kw0]);
            float4 b0 = bp[0], b1 = bp[1], b2 = bp[2];
            float2 v;
            v = make_float2(b0.x,b0.y); CMAC(a0,v,t);
            v = make_float2(b0.z,b0.w); CMAC(a1,v,t);
            v = make_float2(b1.x,b1.y); CMAC(a2,v,t);
            v = make_float2(b1.z,b1.w); CMAC(a3,v,t);
            v = make_float2(b2.x,b2.y); CMAC(a4,v,t);
            v = make_float2(b2.z,b2.w); CMAC(a5,v,t);
        }
        Ash[kw0+0][h]=a0; Ash[kw0+1][h]=a1; Ash[kw0+2][h]=a2;
        Ash[kw0+3][h]=a3; Ash[kw0+4][h]=a4; Ash[kw0+5][h]=a5;
    }
    __syncthreads();
    int wp = threadIdx.x & 31, hg = threadIdx.x >> 5;
    float2 tA[12], tB[12];
    #pragma unroll
    for(int kw=0;kw<12;kw++){ tA[kw]=twW[kw][wp*2]; tB[kw]=twW[kw][wp*2+1]; }
    float ssum=0.f, sq=0.f;
    float2* srow = (float2*)(g_s + (size_t)c*S3 + d*4096);
    for(int h=hg*16; h<hg*16+16; h++){
        float r0=0.f, r1=0.f;
        #pragma unroll
        for(int kw=0;kw<12;kw++){
            float2 a = Ash[kw][h];
            r0 += a.x*tA[kw].x - a.y*tA[kw].y;
            r1 += a.x*tB[kw].x - a.y*tB[kw].y;
        }
        float2 sv = srow[h*32+wp];
        sv.x += r0; sv.y += r1;
        srow[h*32+wp] = sv;
        ssum += sv.x + sv.y; sq += sv.x*sv.x + sv.y*sv.y;
    }
    #pragma unroll
    for(int o=16;o;o>>=1){ ssum += __shfl_xor_sync(0xffffffffu,ssum,o);
                           sq   += __shfl_xor_sync(0xffffffffu,sq,o); }
    if(wp==0){ redS[hg]=ssum; redQ[hg]=sq; }
    __syncthreads();
    if(threadIdx.x==0){
        float S = redS[0]+redS[1]+redS[2]+redS[3];
        float Q = redQ[0]+redQ[1]+redQ[2]+redQ[3];
        int g = c>>3;
        atomicAdd(&g_gn[g*2],   (double)S);
        atomicAdd(&g_gn[g*2+1], (double)Q);
    }
}

__global__ void gn_final_k(){
    int g = threadIdx.x;
    float mu_f=0.f, rs_f=0.f;
    if(g<8){
        double n = 8.0*(double)S3;
        double mu = g_gn[g*2]/n;
        double var = g_gn[g*2+1]/n - mu*mu;
        mu_f = (float)mu; rs_f = (float)(1.0/sqrt(var + 1e-5));
    }
    __syncthreads();
    if(g<8){ g_gnf[g*2]=mu_f; g_gnf[g*2+1]=rs_f; }
    if(g<16) g_gn[g]=0.0;
}

// ---------------- GN-apply + GELU + FiLM + conv(next layer) ----------------
__global__ void __launch_bounds__(256) gn_apply_conv_k(const float* __restrict__ gg, const float* __restrict__ gb,
        int l, const float* __restrict__ cw, const float* __restrict__ cb){
    int s0 = blockIdx.x*128;
    __shared__ float vsh[64][128];
    __shared__ float wshT[64][68];
    int s = threadIdx.x & 127, chalf = threadIdx.x >> 7;
    for(int i=threadIdx.x;i<4096;i+=256) wshT[i&63][i>>6] = cw[i];
    #pragma unroll
    for(int i=0;i<32;i++){
        int cc = i*2 + chalf;
        int g = cc>>3;
        float xv = (g_s[(size_t)cc*S3+s0+s]-g_gnf[g*2])*g_gnf[g*2+1]*__ldg(&gg[cc]) + __ldg(&gb[cc]);
        float y = gelu_f(xv);
        float v = y*(1.f+g_film[(l*64+cc)*2]) + g_film[(l*64+cc)*2+1];
        vsh[cc][s] = v;
        g_v[(size_t)cc*S3+s0+s] = v;
    }
    __syncthreads();
    int o0 = (threadIdx.x>>5)*8, si = (threadIdx.x&31)*4;
    float acc[8][4];
    #pragma unroll
    for(int a=0;a<8;a++){ acc[a][0]=0.f;acc[a][1]=0.f;acc[a][2]=0.f;acc[a][3]=0.f; }
    for(int k=0;k<64;k++){
        float4 v4 = *(const float4*)&vsh[k][si];
        float4 wa = *(const float4*)&wshT[k][o0];
        float4 wb = *(const float4*)&wshT[k][o0+4];
        acc[0][0]+=wa.x*v4.x; acc[0][1]+=wa.x*v4.y; acc[0][2]+=wa.x*v4.z; acc[0][3]+=wa.x*v4.w;
        acc[1][0]+=wa.y*v4.x; acc[1][1]+=wa.y*v4.y; acc[1][2]+=wa.y*v4.z; acc[1][3]+=wa.y*v4.w;
        acc[2][0]+=wa.z*v4.x; acc[2][1]+=wa.z*v4.y; acc[2][2]+=wa.z*v4.z; acc[2][3]+=wa.z*v4.w;
        acc[3][0]+=wa.w*v4.x; acc[3][1]+=wa.w*v4.y; acc[3][2]+=wa.w*v4.z; acc[3][3]+=wa.w*v4.w;
        acc[4][0]+=wb.x*v4.x; acc[4][1]+=wb.x*v4.y; acc[4][2]+=wb.x*v4.z; acc[4][3]+=wb.x*v4.w;
        acc[5][0]+=wb.y*v4.x; acc[5][1]+=wb.y*v4.y; acc[5][2]+=wb.y*v4.z; acc[5][3]+=wb.y*v4.w;
        acc[6][0]+=wb.z*v4.x; acc[6][1]+=wb.z*v4.y; acc[6][2]+=wb.z*v4.z; acc[6][3]+=wb.z*v4.w;
        acc[7][0]+=wb.w*v4.x; acc[7][1]+=wb.w*v4.y; acc[7][2]+=wb.w*v4.z; acc[7][3]+=wb.w*v4.w;
    }
    #pragma unroll
    for(int oi=0;oi<8;oi++){
        float bb = __ldg(&cb[o0+oi]);
        *(float4*)&g_s[(size_t)(o0+oi)*S3 + s0 + si] =
            make_float4(acc[oi][0]+bb, acc[oi][1]+bb, acc[oi][2]+bb, acc[oi][3]+bb);
    }
}

// ---------------- last layer: GN-apply + FiLM + p1 + GELU + p2 ----------------
__global__ void __launch_bounds__(256) gn_apply_head_k(const float* __restrict__ gg, const float* __restrict__ gb,
        int l, const float* __restrict__ w1, const float* __restrict__ b1,
        const float* __restrict__ w2, const float* __restrict__ b2, float* __restrict__ out){
    int s0 = blockIdx.x*64;
    __shared__ float vsh[64][64];
    __shared__ float wshT[64][68];
    __shared__ float w2s[3][128];
    __shared__ float red[16][3][64];
    int s = threadIdx.x & 63, cq = threadIdx.x >> 6;
    for(int i=threadIdx.x;i<384;i+=256){ int j=i>>7, o=i&127; w2s[j][o]=w2[j*128+o]; }
    #pragma unroll
    for(int i=0;i<16;i++){
        int cc = i*4 + cq;
        int g = cc>>3;
        float xv = (g_s[(size_t)cc*S3+s0+s]-g_gnf[g*2])*g_gnf[g*2+1]*__ldg(&gg[cc]) + __ldg(&gb[cc]);
        float y = gelu_f(xv);
        vsh[cc][s] = y*(1.f+g_film[(l*64+cc)*2]) + g_film[(l*64+cc)*2+1];
    }
    int og = threadIdx.x >> 4, sg = threadIdx.x & 15;
    int o0 = og*4, si = sg*4;
    float p[3][4];
    #pragma unroll
    for(int j=0;j<3;j++){ p[j][0]=0.f;p[j][1]=0.f;p[j][2]=0.f;p[j][3]=0.f; }
    for(int half=0; half<2; half++){
        __syncthreads();
        for(int i=threadIdx.x;i<4096;i+=256){ int o=i>>6,k=i&63; wshT[k][o]=w1[(half*64+o)*64+k]; }
        __syncthreads();
        float acc[4][4];
        #pragma unroll
        for(int a=0;a<4;a++){ acc[a][0]=0.f;acc[a][1]=0.f;acc[a][2]=0.f;acc[a][3]=0.f; }
        for(int k=0;k<64;k++){
            float4 v4 = *(const float4*)&vsh[k][si];
            float4 wv = *(const float4*)&wshT[k][o0];
            acc[0][0]+=wv.x*v4.x; acc[0][1]+=wv.x*v4.y; acc[0][2]+=wv.x*v4.z; acc[0][3]+=wv.x*v4.w;
            acc[1][0]+=wv.y*v4.x; acc[1][1]+=wv.y*v4.y; acc[1][2]+=wv.y*v4.z; acc[1][3]+=wv.y*v4.w;
            acc[2][0]+=wv.z*v4.x; acc[2][1]+=wv.z*v4.y; acc[2][2]+=wv.z*v4.z; acc[2][3]+=wv.z*v4.w;
            acc[3][0]+=wv.w*v4.x; acc[3][1]+=wv.w*v4.y; acc[3][2]+=wv.w*v4.z; acc[3][3]+=wv.w*v4.w;
        }
        #pragma unroll
        for(int oi=0;oi<4;oi++){
            int o = half*64 + o0 + oi;
            float bb = __ldg(&b1[o]);
            #pragma unroll
            for(int sx=0;sx<4;sx++){
                float u = gelu_f(acc[oi][sx] + bb);
                p[0][sx] += u*w2s[0][o];
                p[1][sx] += u*w2s[1][o];
                p[2][sx] += u*w2s[2][o];
            }
        }
    }
    #pragma unroll
    for(int j=0;j<3;j++){
        red[og][j][si+0]=p[j][0]; red[og][j][si+1]=p[j][1];
        red[og][j][si+2]=p[j][2]; red[og][j][si+3]=p[j][3];
    }
    __syncthreads();
    if(threadIdx.x < 64){
        int ss = threadIdx.x;
        #pragma unroll
        for(int j=0;j<3;j++){
            float acc = __ldg(&b2[j]);
            #pragma unroll
            for(int gq=0;gq<16;gq++) acc += red[gq][j][ss];
            out[(size_t)j*S3 + s0 + ss] = acc;
        }
    }
}

// ---------------- launch ----------------
extern "C" void kernel_launch(void* const* d_in, const int* in_sizes, int n_in,
                              void* d_out, int out_size){
    const float* x      = (const float*)d_in[0];
    const float* latent = (const float*)d_in[1];
    const float* lift_w = (const float*)d_in[2];
    const float* lift_b = (const float*)d_in[3];
    const float* sc_w1  = (const float*)d_in[4];
    const float* sc_w2  = (const float*)d_in[5];
    const float* sc_w3  = (const float*)d_in[6];
    const float* sc_w4  = (const float*)d_in[7];
    const float* conv_w = (const float*)d_in[8];
    const float* conv_b = (const float*)d_in[9];
    const float* gn_g   = (const float*)d_in[10];
    const float* gn_b   = (const float*)d_in[11];
    const float* p1_w   = (const float*)d_in[12];
    const float* p1_b   = (const float*)d_in[13];
    const float* p2_w   = (const float*)d_in[14];
    const float* p2_b   = (const float*)d_in[15];
    const float* c1_w   = (const float*)d_in[16];
    const float* c1_b   = (const float*)d_in[17];
    const float* c2_w   = (const float*)d_in[18];
    const float* c2_b   = (const float*)d_in[19];
    float* out = (float*)d_out;

    init_tables_k<<<6,256>>>();
    film1_k<<<128,256>>>(latent, c1_w, c1_b);
    film2_k<<<48,256>>>(c2_w, c2_b);
    lift_conv_k<<<2048,256>>>(x, lift_w, lift_b, conv_w, conv_b);

    const size_t WOFF = (size_t)64*64*12*12*12*2;
    for(int l=0;l<3;l++){
        fwdWH_k<<<dim3(64,64),128>>>();
        fwdD_k<<<dim3(24,64),128>>>();
        mix_k<<<dim3(108,8),256>>>(sc_w1 + l*WOFF, sc_w2 + l*WOFF,
                                   sc_w3 + l*WOFF, sc_w4 + l*WOFF);
        invD_k<<<dim3(24,64),128>>>();
        invHW_gn_k<<<dim3(64,64),128>>>();
        gn_final_k<<<1,32>>>();
        if(l<2)
            gn_apply_conv_k<<<2048,256>>>(gn_g + l*64, gn_b + l*64, l,
                                          conv_w + (l+1)*4096, conv_b + (l+1)*64);
        else
            gn_apply_head_k<<<4096,256>>>(gn_g + l*64, gn_b + l*64, l,
                                          p1_w, p1_b, p2_w, p2_b, out);
    }
}